// round 3
// baseline (speedup 1.0000x reference)
#include <cuda_runtime.h>

// ConditionalFeedForward: MoE SwiGLU, compute only routed (token, slot) pairs.
// T=512, TOPK=2, E=8, H=2816, D=1024, fp32 everywhere.
//
// Pipeline (3 graph-capturable launches, no allocations):
//   1) route_kernel : bucket the 1024 (token,slot) pairs by expert
//                     (detects int32 vs int64 expert_indices on device)
//   2) gemm1_kernel : h = silu(x . w1[e]^T) * (x . w3[e]^T)  -> g_hbuf
//   3) gemm2_kernel : out[pair] = h . w2[e]                  -> d_out

namespace {
constexpr int kE = 8;
constexpr int kT = 512;
constexpr int kTOPK = 2;
constexpr int kH = 2816;
constexpr int kD = 1024;
constexpr int NP = kT * kTOPK;   // 1024 routed pairs

// GEMM1 tiles: 64 tokens x 128 h rows, k-chunk 32. 256 threads, micro 4x8.
constexpr int G1_TT = 64;
constexpr int G1_BH = 128;
constexpr int G1_DK = 32;

// GEMM2 tiles: 32 tokens x 128 outs, k-chunk 32. 256 threads, micro 2x8.
constexpr int G2_TT = 32;
constexpr int G2_BI = 128;
constexpr int G2_HK = 32;
}

__device__ int   g_off[kE + 1];
__device__ int   g_pairs[NP];                        // pair ids sorted by expert
__device__ float g_hbuf[(size_t)NP * kH];            // 11.5 MB scratch

// ---------------------------------------------------------------------------
// Routing: counts + offsets + scatter, one block of 1024 threads.
// expert_indices may be int32 (JAX x64 disabled -> most likely) or int64.
// Detect on device: read the first NP/2 words as int64 (4KB — in bounds for
// either dtype). Genuine int64 data has every value in [0, E); int32 data
// interpreted as int64 produces huge values whenever the odd word != 0
// (P[all zero] ~ 8^-512 ~ 0).
// ---------------------------------------------------------------------------
__global__ void route_kernel(const void* __restrict__ eidx_raw) {
    __shared__ int cnt[kE];
    __shared__ int cur[kE];
    __shared__ int not64;
    int tid = threadIdx.x;
    if (tid < kE) cnt[tid] = 0;
    if (tid == 0) not64 = 0;
    __syncthreads();

    const long long* p64 = (const long long*)eidx_raw;
    if (tid < NP / 2) {
        long long v = p64[tid];
        if (v < 0 || v >= kE) not64 = 1;   // benign race: any writer sets 1
    }
    __syncthreads();

    int e;
    if (not64) e = ((const int*)eidx_raw)[tid];
    else       e = (int)p64[tid];

    atomicAdd(&cnt[e], 1);
    __syncthreads();
    if (tid == 0) {
        int o = 0;
        for (int i = 0; i < kE; i++) { g_off[i] = o; cur[i] = o; o += cnt[i]; }
        g_off[kE] = o;
    }
    __syncthreads();
    int p = atomicAdd(&cur[e], 1);
    g_pairs[p] = tid;   // pair id == t*TOPK + slot
}

// ---------------------------------------------------------------------------
// GEMM1 + SwiGLU.  grid.x = E * (H/128) = 176, grid.y = 2 (token-tile stride)
// Block computes [64 tokens x 128 h] of both x.w1^T and x.w3^T, then fuses
// silu(h1)*h3 into g_hbuf (indexed by sorted pair position).
// ---------------------------------------------------------------------------
__global__ __launch_bounds__(256, 2)
void gemm1_kernel(const float* __restrict__ x,
                  const float* __restrict__ w1,
                  const float* __restrict__ w3) {
    __shared__ float xs [G1_DK][G1_TT + 1];
    __shared__ float w1s[G1_DK][G1_BH + 1];
    __shared__ float w3s[G1_DK][G1_BH + 1];
    __shared__ int   toks[G1_TT];

    const int ntiles_h = kH / G1_BH;                 // 22
    const int e  = blockIdx.x / ntiles_h;
    const int hb = (blockIdx.x % ntiles_h) * G1_BH;
    const int base = g_off[e];
    const int nt   = g_off[e + 1] - base;

    const int tid = threadIdx.x;
    const int tx  = tid & 15;     // h dim (8 rows strided by 16)
    const int ty  = tid >> 4;     // token dim (4 contiguous tokens)

    const float* w1e = w1 + ((size_t)e * kH + hb) * kD;
    const float* w3e = w3 + ((size_t)e * kH + hb) * kD;

    for (int t0 = blockIdx.y * G1_TT; t0 < nt; t0 += gridDim.y * G1_TT) {
        const int ntt = min(G1_TT, nt - t0);

        __syncthreads();
        if (tid < G1_TT)
            toks[tid] = (tid < ntt) ? (g_pairs[base + t0 + tid] / kTOPK) : 0;
        __syncthreads();

        float acc1[4][8], acc3[4][8];
        #pragma unroll
        for (int j = 0; j < 4; j++)
            #pragma unroll
            for (int m = 0; m < 8; m++) { acc1[j][m] = 0.f; acc3[j][m] = 0.f; }

        for (int d0 = 0; d0 < kD; d0 += G1_DK) {
            // x chunk: 64 tokens x 32 k   (2048 elems, 8 per thread)
            #pragma unroll
            for (int r = 0; r < (G1_TT * G1_DK) / 256; r++) {
                int i = tid + r * 256;
                int t = i / G1_DK, k = i % G1_DK;
                xs[k][t] = x[(size_t)toks[t] * kD + d0 + k];
            }
            // weight chunks: 128 h x 32 k (4096 elems, 16 per thread each)
            #pragma unroll
            for (int r = 0; r < (G1_BH * G1_DK) / 256; r++) {
                int i = tid + r * 256;
                int h = i / G1_DK, k = i % G1_DK;
                size_t go = (size_t)h * kD + d0 + k;
                w1s[k][h] = w1e[go];
                w3s[k][h] = w3e[go];
            }
            __syncthreads();

            #pragma unroll
            for (int kk = 0; kk < G1_DK; kk++) {
                float a[4], b1[8], b3[8];
                #pragma unroll
                for (int j = 0; j < 4; j++) a[j] = xs[kk][ty * 4 + j];
                #pragma unroll
                for (int m = 0; m < 8; m++) {
                    b1[m] = w1s[kk][tx + 16 * m];
                    b3[m] = w3s[kk][tx + 16 * m];
                }
                #pragma unroll
                for (int j = 0; j < 4; j++)
                    #pragma unroll
                    for (int m = 0; m < 8; m++) {
                        acc1[j][m] += a[j] * b1[m];
                        acc3[j][m] += a[j] * b3[m];
                    }
            }
            __syncthreads();
        }

        // Epilogue: silu(h1) * h3 -> hbuf (row = sorted pair position)
        #pragma unroll
        for (int j = 0; j < 4; j++) {
            int t = ty * 4 + j;
            if (t < ntt) {
                size_t row = (size_t)(base + t0 + t) * kH + hb;
                #pragma unroll
                for (int m = 0; m < 8; m++) {
                    float z = acc1[j][m];
                    float s = z / (1.0f + __expf(-z));   // silu
                    g_hbuf[row + tx + 16 * m] = s * acc3[j][m];
                }
            }
        }
    }
}

// ---------------------------------------------------------------------------
// GEMM2.  grid.x = E * (D/128) = 64, grid.y = 4 (token-tile stride) -> 256 blocks
// out[pair, i] = sum_h hbuf[p, h] * w2[e, h, i]
// ---------------------------------------------------------------------------
__global__ __launch_bounds__(256, 2)
void gemm2_kernel(const float* __restrict__ w2, float* __restrict__ out) {
    __shared__ float as[G2_HK][G2_TT + 1];
    __shared__ float bs[G2_HK][G2_BI + 1];
    __shared__ int   prs[G2_TT];

    const int ntiles_i = kD / G2_BI;                 // 8
    const int e  = blockIdx.x / ntiles_i;
    const int ib = (blockIdx.x % ntiles_i) * G2_BI;
    const int base = g_off[e];
    const int nt   = g_off[e + 1] - base;

    const int tid = threadIdx.x;
    const int tx  = tid & 15;     // i dim (8 strided by 16)
    const int ty  = tid >> 4;     // token dim (2 contiguous)

    const float* w2e = w2 + (size_t)e * kH * kD + ib;

    for (int t0 = blockIdx.y * G2_TT; t0 < nt; t0 += gridDim.y * G2_TT) {
        const int ntt = min(G2_TT, nt - t0);

        __syncthreads();
        if (tid < G2_TT)
            prs[tid] = (tid < ntt) ? g_pairs[base + t0 + tid] : 0;
        __syncthreads();

        float acc[2][8];
        #pragma unroll
        for (int j = 0; j < 2; j++)
            #pragma unroll
            for (int m = 0; m < 8; m++) acc[j][m] = 0.f;

        for (int h0 = 0; h0 < kH; h0 += G2_HK) {
            // A chunk from hbuf: 32 tokens x 32 k (1024 elems, 4 per thread)
            #pragma unroll
            for (int r = 0; r < (G2_TT * G2_HK) / 256; r++) {
                int i = tid + r * 256;
                int t = i / G2_HK, k = i % G2_HK;
                int tc = (t < ntt) ? t : 0;
                as[k][t] = g_hbuf[(size_t)(base + t0 + tc) * kH + h0 + k];
            }
            // B chunk from w2: 32 k x 128 i (4096 elems, 16 per thread) — coalesced
            #pragma unroll
            for (int r = 0; r < (G2_HK * G2_BI) / 256; r++) {
                int i  = tid + r * 256;
                int k  = i / G2_BI, i2 = i % G2_BI;
                bs[k][i2] = w2e[(size_t)(h0 + k) * kD + i2];
            }
            __syncthreads();

            #pragma unroll
            for (int kk = 0; kk < G2_HK; kk++) {
                float a[2], b[8];
                #pragma unroll
                for (int j = 0; j < 2; j++) a[j] = as[kk][ty * 2 + j];
                #pragma unroll
                for (int m = 0; m < 8; m++) b[m] = bs[kk][tx + 16 * m];
                #pragma unroll
                for (int j = 0; j < 2; j++)
                    #pragma unroll
                    for (int m = 0; m < 8; m++) acc[j][m] += a[j] * b[m];
            }
            __syncthreads();
        }

        #pragma unroll
        for (int j = 0; j < 2; j++) {
            int t = ty * 2 + j;
            if (t < ntt) {
                size_t row = (size_t)prs[t] * kD + ib;
                #pragma unroll
                for (int m = 0; m < 8; m++)
                    out[row + tx + 16 * m] = acc[j][m];
            }
        }
    }
}

// ---------------------------------------------------------------------------
extern "C" void kernel_launch(void* const* d_in, const int* in_sizes, int n_in,
                              void* d_out, int out_size) {
    const float* x    = (const float*)d_in[0];
    const void*  eidx = d_in[1];
    const float* w1   = (const float*)d_in[2];
    const float* w2   = (const float*)d_in[3];
    const float* w3   = (const float*)d_in[4];
    float*       out  = (float*)d_out;

    route_kernel<<<1, NP>>>(eidx);
    gemm1_kernel<<<dim3(kE * (kH / G1_BH), 2), 256>>>(x, w1, w3);
    gemm2_kernel<<<dim3(kE * (kD / G2_BI), 4), 256>>>(w2, out);
}

// round 4
// speedup vs baseline: 5.0144x; 5.0144x over previous
#include <cuda_runtime.h>
#include <cuda_fp16.h>
#include <cstdint>

// MoE SwiGLU via fp16 tensor cores (mma.m16n8k16, fp32 accum), fused
// fp32->fp16 conversion in the smem load path. Weights stay fp32 in HBM.
//   1) route_kernel : bucket 1024 (token,slot) pairs by expert
//   2) gemm1_kernel : hbuf(fp16) = silu(x.w1[e]^T) * (x.w3[e]^T)
//   3) gemm2_kernel : out = hbuf . w2[e]   (fp32 out)

namespace {
constexpr int kE = 8;
constexpr int kTOPK = 2;
constexpr int kH = 2816;
constexpr int kD = 1024;
constexpr int NP = 1024;

// GEMM1: BM=128 tokens, BN=128 h (x2 matrices), BK=16
constexpr int G1_NT_H = kH / 128;       // 22 h-tiles
constexpr int G1_XS = 24;               // smem row stride in fp16 (16 + 8 pad)
// GEMM2: BM=128 tokens, BN=64 d, BK=32
constexpr int G2_NT_D = kD / 64;        // 16 d-tiles
constexpr int G2_AS = 40;               // A row stride fp16 (32 + 8 pad)
constexpr int G2_BS = 72;               // B row stride fp16 (64 + 8 pad)
}

__device__ int    g_off[kE + 1];
__device__ int    g_pairs[NP];
__device__ __half g_hbuf[(size_t)NP * kH];   // 5.77 MB fp16 intermediate

// ---------------------------------------------------------------------------
// helpers
// ---------------------------------------------------------------------------
__device__ __forceinline__ uint32_t s2u(const void* p) {
    return (uint32_t)__cvta_generic_to_shared(p);
}
__device__ __forceinline__ void ldsm_x4(uint32_t r[4], uint32_t addr) {
    asm volatile("ldmatrix.sync.aligned.m8n8.x4.shared.b16 {%0,%1,%2,%3}, [%4];"
                 : "=r"(r[0]), "=r"(r[1]), "=r"(r[2]), "=r"(r[3]) : "r"(addr));
}
__device__ __forceinline__ void ldsm_x4_t(uint32_t r[4], uint32_t addr) {
    asm volatile("ldmatrix.sync.aligned.m8n8.x4.trans.shared.b16 {%0,%1,%2,%3}, [%4];"
                 : "=r"(r[0]), "=r"(r[1]), "=r"(r[2]), "=r"(r[3]) : "r"(addr));
}
__device__ __forceinline__ void mma16816(float c[4], const uint32_t a[4],
                                         uint32_t b0, uint32_t b1) {
    asm volatile(
        "mma.sync.aligned.m16n8k16.row.col.f32.f16.f16.f32 "
        "{%0,%1,%2,%3},{%4,%5,%6,%7},{%8,%9},{%0,%1,%2,%3};"
        : "+f"(c[0]), "+f"(c[1]), "+f"(c[2]), "+f"(c[3])
        : "r"(a[0]), "r"(a[1]), "r"(a[2]), "r"(a[3]), "r"(b0), "r"(b1));
}
__device__ __forceinline__ uint32_t h2u(__half2 h) {
    return *reinterpret_cast<uint32_t*>(&h);
}
__device__ __forceinline__ float silu(float z) {
    return z / (1.0f + __expf(-z));
}

// ---------------------------------------------------------------------------
// Routing (int32/int64 dtype auto-detect, as validated in R3)
// ---------------------------------------------------------------------------
__global__ void route_kernel(const void* __restrict__ eidx_raw) {
    __shared__ int cnt[kE];
    __shared__ int cur[kE];
    __shared__ int not64;
    int tid = threadIdx.x;
    if (tid < kE) cnt[tid] = 0;
    if (tid == 0) not64 = 0;
    __syncthreads();

    const long long* p64 = (const long long*)eidx_raw;
    if (tid < NP / 2) {
        long long v = p64[tid];
        if (v < 0 || v >= kE) not64 = 1;
    }
    __syncthreads();

    int e = not64 ? ((const int*)eidx_raw)[tid] : (int)p64[tid];

    atomicAdd(&cnt[e], 1);
    __syncthreads();
    if (tid == 0) {
        int o = 0;
        for (int i = 0; i < kE; i++) { g_off[i] = o; cur[i] = o; o += cnt[i]; }
        g_off[kE] = o;
    }
    __syncthreads();
    int p = atomicAdd(&cur[e], 1);
    g_pairs[p] = tid;
}

// ---------------------------------------------------------------------------
// GEMM1 + SwiGLU (fp16 HMMA).
// grid.x = 2 strips * 22 htiles * 8 experts = 352 (strip fastest -> L2 reuse)
// Block tile: 128 tokens x 128 h (both w1 and w3), K=1024 in 64 stages of 16.
// 8 warps: 2 (m) x 4 (n); warp tile 64m x 32n per matrix.
// ---------------------------------------------------------------------------
__global__ __launch_bounds__(256, 1)
void gemm1_kernel(const float* __restrict__ x,
                  const float* __restrict__ w1,
                  const float* __restrict__ w3) {
    __shared__ __half Xs [2][128][G1_XS];
    __shared__ __half W1s[2][128][G1_XS];
    __shared__ __half W3s[2][128][G1_XS];
    __shared__ int    toks[128];

    const int bx    = blockIdx.x;
    const int strip = bx & 1;
    const int ht    = (bx >> 1) % G1_NT_H;
    const int e     = bx / (2 * G1_NT_H);
    const int hb    = ht * 128;
    const int base  = g_off[e];
    const int nt    = g_off[e + 1] - base;

    const int tid  = threadIdx.x;
    const int lane = tid & 31;
    const int wid  = tid >> 5;
    const int wm   = wid & 1;       // 2 m-warps (64 rows each)
    const int wn   = wid >> 1;      // 4 n-warps (32 cols each)

    const float* w1e = w1 + ((size_t)e * kH + hb) * kD;
    const float* w3e = w3 + ((size_t)e * kH + hb) * kD;

    // ldmatrix source coords (row within tile-group, col half)
    const int lrow = lane & 15;
    const int lcol = (lane >> 4) * 8;

    for (int t0 = strip * 128; t0 < nt; t0 += 256) {
        const int ntt = min(128, nt - t0);

        if (tid < 128)
            toks[tid] = g_pairs[base + t0 + min(tid, ntt - 1)] / kTOPK;
        __syncthreads();

        float4 st[6];
        // -- stage loaders ---------------------------------------------------
        auto ldg_stage = [&](int d0) {
            #pragma unroll
            for (int r = 0; r < 2; r++) {
                int i = tid + r * 256;           // 512 float4 per region
                int m = i >> 2, k4 = i & 3;
                st[r]     = *(const float4*)&x[(size_t)toks[m] * kD + d0 + k4 * 4];
                st[2 + r] = *(const float4*)&w1e[(size_t)m * kD + d0 + k4 * 4];
                st[4 + r] = *(const float4*)&w3e[(size_t)m * kD + d0 + k4 * 4];
            }
        };
        auto sts_stage = [&](int s) {
            #pragma unroll
            for (int r = 0; r < 2; r++) {
                int i = tid + r * 256;
                int m = i >> 2, k4 = i & 3;
                {
                    float4 v = st[r];
                    uint2 u = { h2u(__floats2half2_rn(v.x, v.y)),
                                h2u(__floats2half2_rn(v.z, v.w)) };
                    *(uint2*)&Xs[s][m][k4 * 4] = u;
                }
                {
                    float4 v = st[2 + r];
                    uint2 u = { h2u(__floats2half2_rn(v.x, v.y)),
                                h2u(__floats2half2_rn(v.z, v.w)) };
                    *(uint2*)&W1s[s][m][k4 * 4] = u;
                }
                {
                    float4 v = st[4 + r];
                    uint2 u = { h2u(__floats2half2_rn(v.x, v.y)),
                                h2u(__floats2half2_rn(v.z, v.w)) };
                    *(uint2*)&W3s[s][m][k4 * 4] = u;
                }
            }
        };
        // --------------------------------------------------------------------

        ldg_stage(0);
        sts_stage(0);
        __syncthreads();

        float acc1[4][4][4], acc3[4][4][4];
        #pragma unroll
        for (int mt = 0; mt < 4; mt++)
            #pragma unroll
            for (int ntl = 0; ntl < 4; ntl++)
                #pragma unroll
                for (int q = 0; q < 4; q++) { acc1[mt][ntl][q] = 0.f; acc3[mt][ntl][q] = 0.f; }

        const int NST = kD / 16;   // 64
        for (int ks = 0; ks < NST; ks++) {
            int s = ks & 1;
            if (ks + 1 < NST) ldg_stage((ks + 1) * 16);

            uint32_t a[4][4], b1[2][4], b3[2][4];
            #pragma unroll
            for (int mt = 0; mt < 4; mt++)
                ldsm_x4(a[mt], s2u(&Xs[s][wm * 64 + mt * 16 + lrow][lcol]));
            #pragma unroll
            for (int g2 = 0; g2 < 2; g2++) {
                ldsm_x4(b1[g2], s2u(&W1s[s][wn * 32 + g2 * 16 + lrow][lcol]));
                ldsm_x4(b3[g2], s2u(&W3s[s][wn * 32 + g2 * 16 + lrow][lcol]));
            }
            #pragma unroll
            for (int mt = 0; mt < 4; mt++)
                #pragma unroll
                for (int ntl = 0; ntl < 4; ntl++) {
                    int g2 = ntl >> 1, sub = ntl & 1;
                    mma16816(acc1[mt][ntl], a[mt], b1[g2][sub], b1[g2][2 + sub]);
                    mma16816(acc3[mt][ntl], a[mt], b3[g2][sub], b3[g2][2 + sub]);
                }

            if (ks + 1 < NST) sts_stage(s ^ 1);
            __syncthreads();
        }

        // epilogue: silu(h1)*h3 -> g_hbuf (fp16)
        #pragma unroll
        for (int mt = 0; mt < 4; mt++) {
            int row0 = wm * 64 + mt * 16 + (lane >> 2);
            #pragma unroll
            for (int ntl = 0; ntl < 4; ntl++) {
                int col = hb + wn * 32 + ntl * 8 + (lane & 3) * 2;
                if (row0 < ntt) {
                    float v0 = silu(acc1[mt][ntl][0]) * acc3[mt][ntl][0];
                    float v1 = silu(acc1[mt][ntl][1]) * acc3[mt][ntl][1];
                    *(__half2*)&g_hbuf[(size_t)(base + t0 + row0) * kH + col] =
                        __floats2half2_rn(v0, v1);
                }
                if (row0 + 8 < ntt) {
                    float v0 = silu(acc1[mt][ntl][2]) * acc3[mt][ntl][2];
                    float v1 = silu(acc1[mt][ntl][3]) * acc3[mt][ntl][3];
                    *(__half2*)&g_hbuf[(size_t)(base + t0 + row0 + 8) * kH + col] =
                        __floats2half2_rn(v0, v1);
                }
            }
        }
        __syncthreads();
    }
}

// ---------------------------------------------------------------------------
// GEMM2 (fp16 HMMA): out[pair, d] = hbuf[p, :] . w2[e, :, d]
// grid.x = 2 strips * 16 dtiles * 8 experts = 256
// Block tile: 128 tokens x 64 d, K=2816 in 88 stages of 32.
// 8 warps: 4 (m) x 2 (n); warp tile 32m x 32n.
// ---------------------------------------------------------------------------
__global__ __launch_bounds__(256, 1)
void gemm2_kernel(const float* __restrict__ w2, float* __restrict__ out) {
    __shared__ __half As[2][128][G2_AS];
    __shared__ __half Bs[2][32][G2_BS];
    __shared__ int    prs[128];

    const int bx    = blockIdx.x;
    const int strip = bx & 1;
    const int dt    = (bx >> 1) % G2_NT_D;
    const int e     = bx / (2 * G2_NT_D);
    const int ib    = dt * 64;
    const int base  = g_off[e];
    const int nt    = g_off[e + 1] - base;

    const int tid  = threadIdx.x;
    const int lane = tid & 31;
    const int wid  = tid >> 5;
    const int wm   = wid & 3;       // 4 m-warps (32 rows)
    const int wn   = wid >> 2;      // 2 n-warps (32 cols)

    const float* w2e = w2 + (size_t)e * kH * kD + ib;

    const int lrow = lane & 15;
    const int lcol = (lane >> 4) * 8;
    // trans-ldmatrix coords for B
    const int ti   = lane >> 3;          // tile 0..3
    const int trow = (ti >> 1) * 8 + (lane & 7);
    const int tcol = (ti & 1) * 8;

    for (int t0 = strip * 128; t0 < nt; t0 += 256) {
        const int ntt = min(128, nt - t0);

        if (tid < 128)
            prs[tid] = g_pairs[base + t0 + min(tid, ntt - 1)];
        __syncthreads();

        uint4  stA[2];
        float4 stB[2];
        auto ldg_stage = [&](int h0) {
            #pragma unroll
            for (int r = 0; r < 2; r++) {
                int i = tid + r * 256;           // A: 512 uint4 (8 halves)
                int m = i >> 2, c8 = i & 3;
                int tc = min(m, ntt - 1);
                stA[r] = *(const uint4*)&g_hbuf[(size_t)(base + t0 + tc) * kH + h0 + c8 * 8];
                int h = i >> 4, d4 = i & 15;     // B: 512 float4
                stB[r] = *(const float4*)&w2e[(size_t)(h0 + h) * kD + d4 * 4];
            }
        };
        auto sts_stage = [&](int s) {
            #pragma unroll
            for (int r = 0; r < 2; r++) {
                int i = tid + r * 256;
                int m = i >> 2, c8 = i & 3;
                *(uint4*)&As[s][m][c8 * 8] = stA[r];
                int h = i >> 4, d4 = i & 15;
                float4 v = stB[r];
                uint2 u = { h2u(__floats2half2_rn(v.x, v.y)),
                            h2u(__floats2half2_rn(v.z, v.w)) };
                *(uint2*)&Bs[s][h][d4 * 4] = u;
            }
        };

        ldg_stage(0);
        sts_stage(0);
        __syncthreads();

        float acc[2][4][4];
        #pragma unroll
        for (int mt = 0; mt < 2; mt++)
            #pragma unroll
            for (int ntl = 0; ntl < 4; ntl++)
                #pragma unroll
                for (int q = 0; q < 4; q++) acc[mt][ntl][q] = 0.f;

        const int NST = kH / 32;   // 88
        for (int ks = 0; ks < NST; ks++) {
            int s = ks & 1;
            if (ks + 1 < NST) ldg_stage((ks + 1) * 32);

            #pragma unroll
            for (int kk = 0; kk < 2; kk++) {     // two k16 chunks
                uint32_t a[2][4], b[2][4];
                #pragma unroll
                for (int mt = 0; mt < 2; mt++)
                    ldsm_x4(a[mt], s2u(&As[s][wm * 32 + mt * 16 + lrow][kk * 16 + lcol]));
                #pragma unroll
                for (int g2 = 0; g2 < 2; g2++)
                    ldsm_x4_t(b[g2], s2u(&Bs[s][kk * 16 + trow][wn * 32 + g2 * 16 + tcol]));
                #pragma unroll
                for (int mt = 0; mt < 2; mt++)
                    #pragma unroll
                    for (int ntl = 0; ntl < 4; ntl++) {
                        int g2 = ntl >> 1, sub = ntl & 1;
                        mma16816(acc[mt][ntl], a[mt], b[g2][sub], b[g2][2 + sub]);
                    }
            }

            if (ks + 1 < NST) sts_stage(s ^ 1);
            __syncthreads();
        }

        // epilogue: fp32 stores to out[pair][d]
        #pragma unroll
        for (int mt = 0; mt < 2; mt++) {
            int row0 = wm * 32 + mt * 16 + (lane >> 2);
            #pragma unroll
            for (int ntl = 0; ntl < 4; ntl++) {
                int col = ib + wn * 32 + ntl * 8 + (lane & 3) * 2;
                if (row0 < ntt) {
                    float2 v = { acc[mt][ntl][0], acc[mt][ntl][1] };
                    *(float2*)&out[(size_t)prs[row0] * kD + col] = v;
                }
                if (row0 + 8 < ntt) {
                    float2 v = { acc[mt][ntl][2], acc[mt][ntl][3] };
                    *(float2*)&out[(size_t)prs[row0 + 8] * kD + col] = v;
                }
            }
        }
        __syncthreads();
    }
}

// ---------------------------------------------------------------------------
extern "C" void kernel_launch(void* const* d_in, const int* in_sizes, int n_in,
                              void* d_out, int out_size) {
    const float* x    = (const float*)d_in[0];
    const void*  eidx = d_in[1];
    const float* w1   = (const float*)d_in[2];
    const float* w2   = (const float*)d_in[3];
    const float* w3   = (const float*)d_in[4];
    float*       out  = (float*)d_out;

    route_kernel<<<1, NP>>>(eidx);
    gemm1_kernel<<<2 * G1_NT_H * kE, 256>>>(x, w1, w3);
    gemm2_kernel<<<2 * G2_NT_D * kE, 256>>>(w2, out);
}